// round 12
// baseline (speedup 1.0000x reference)
#include <cuda_runtime.h>
#include <cuda_bf16.h>
#include <math.h>

#define NB   4
#define BSZ  8
#define NF   128
#define WDIM 512
#define IMG  256

typedef unsigned long long ull;

// ---------------- scratch (static device globals; no allocation) -------------
__device__ float g_xa[BSZ * NF * IMG * IMG];
__device__ float g_xb[BSZ * NF * IMG * IMG];
__device__ float g_s[NB * BSZ * NF];
__device__ float g_rgb[BSZ * (32*32 + 64*64 + 128*128 + 256*256)];
// pre-split modulated weights, interleaved {hi_pair, lo_pair} per ull:
// [b][chunk(ci/16)][co][tap k][ci2 pair]
__device__ ull g_ws[BSZ * 8 * NF * 72];

// ---------------- helpers ----------------------------------------------------
__device__ __forceinline__ void split2(float v0, float v1,
                                       unsigned int& hi, unsigned int& lo) {
    __nv_bfloat16 h0 = __float2bfloat16(v0);
    __nv_bfloat16 h1 = __float2bfloat16(v1);
    float r0 = v0 - __bfloat162float(h0);
    float r1 = v1 - __bfloat162float(h1);
    __nv_bfloat16 l0 = __float2bfloat16(r0);
    __nv_bfloat16 l1 = __float2bfloat16(r1);
    hi = (unsigned int)__bfloat16_as_ushort(h0) |
         ((unsigned int)__bfloat16_as_ushort(h1) << 16);
    lo = (unsigned int)__bfloat16_as_ushort(l0) |
         ((unsigned int)__bfloat16_as_ushort(l1) << 16);
}

__device__ __forceinline__ void mma16816(float* d, const unsigned int* a,
                                         const unsigned int* b) {
    asm volatile(
        "mma.sync.aligned.m16n8k16.row.col.f32.bf16.bf16.f32 "
        "{%0,%1,%2,%3}, {%4,%5,%6,%7}, {%8,%9}, {%0,%1,%2,%3};\n"
        : "+f"(d[0]), "+f"(d[1]), "+f"(d[2]), "+f"(d[3])
        : "r"(a[0]), "r"(a[1]), "r"(a[2]), "r"(a[3]), "r"(b[0]), "r"(b[1]));
}

__device__ __forceinline__ void cp16(void* smem_dst, const void* gsrc) {
    unsigned int sa = (unsigned int)__cvta_generic_to_shared(smem_dst);
    asm volatile("cp.async.cg.shared.global [%0], [%1], 16;\n"
                 :: "r"(sa), "l"(gsrc));
}
__device__ __forceinline__ void cp_commit() {
    asm volatile("cp.async.commit_group;\n");
}
__device__ __forceinline__ void cp_wait0() {
    asm volatile("cp.async.wait_group 0;\n");
}

// ---------------- styles -----------------------------------------------------
__global__ void k_style(const float* __restrict__ w, const float* __restrict__ tsw,
                        const float* __restrict__ tsb) {
    int i = blockIdx.x / BSZ, b = blockIdx.x % BSZ;
    int c = threadIdx.x;
    __shared__ float sw[WDIM];
    for (int d = threadIdx.x; d < WDIM; d += blockDim.x)
        sw[d] = w[(i * BSZ + b) * WDIM + d];
    __syncthreads();
    const float* tw = tsw + (i * NF + c) * WDIM;
    float acc = 0.f;
    #pragma unroll 4
    for (int d = 0; d < WDIM; d++) acc += sw[d] * tw[d];
    const float cl = 0.044194173824159216f;   // 1/sqrt(512)
    g_s[(i * BSZ + b) * NF + c] = acc * cl + tsb[i * NF + c];
}

// ---- modulated + demodulated weights -> interleaved bf16 hi/lo ull ----------
__global__ void k_modw(const float* __restrict__ conv_w, int i, int j) {
    int b = blockIdx.x / NF, co = blockIdx.x % NF;
    const float* wsrc = conv_w + (((size_t)(i * 2 + j) * NF + co) * NF) * 9;
    const float* s = g_s + (i * BSZ + b) * NF;
    const float c = 0.029462782549439483f;    // 1/sqrt(128*9)
    __shared__ float buf[NF * 9];
    __shared__ float red[32];
    float ss = 0.f;
    for (int t = threadIdx.x; t < NF * 9; t += blockDim.x) {
        float v = wsrc[t] * c * s[t / 9];
        buf[t] = v;
        ss += v * v;
    }
    for (int o = 16; o; o >>= 1) ss += __shfl_xor_sync(0xffffffffu, ss, o);
    if ((threadIdx.x & 31) == 0) red[threadIdx.x >> 5] = ss;
    __syncthreads();
    if (threadIdx.x < 32) {
        float v = (threadIdx.x < (blockDim.x >> 5)) ? red[threadIdx.x] : 0.f;
        for (int o = 16; o; o >>= 1) v += __shfl_xor_sync(0xffffffffu, v, o);
        if (threadIdx.x == 0) red[0] = v;
    }
    __syncthreads();
    float dem = rsqrtf(red[0] + 1e-8f);
    for (int e = threadIdx.x; e < 576; e += blockDim.x) {
        int ci2g = e / 9, k = e - ci2g * 9;
        int ci = ci2g * 2;
        float v0 = buf[ci * 9 + k] * dem;
        float v1 = buf[ci * 9 + 9 + k] * dem;
        unsigned int hi, lo;
        split2(v0, v1, hi, lo);
        int chunk = ci2g >> 3, p = ci2g & 7;
        size_t idx = (((size_t)(b * 8 + chunk) * NF + co) * 9 + k) * 8 + p;
        g_ws[idx] = (ull)hi | ((ull)lo << 32);
    }
}

// ---------------- initial constant -------------------------------------------
__global__ void k_init(const float* __restrict__ ic, float* __restrict__ x) {
    int idx = blockIdx.x * blockDim.x + threadIdx.x;
    if (idx >= BSZ * NF * 32 * 32) return;
    int per = NF * 32 * 32;
    float v = ic[idx % per];
    x[idx] = v > 0.f ? v : 0.f;
}

// ---------------- tensor-core modulated conv3x3, pipelined, fused upsample ---
// 256 threads = 8 warps: warp w -> co group w*16, FULL 8 rows x NCB col-blocks
// (fat warp tile: 24*NCB MMAs amortize each tap's A-loads + addressing).
// smem (ull): s_w double-buffered [2][NF][76]  then s_x [10][HW][12]
#define W_STRIDE 76
#define X_PXS    12
#define W_BUF_ULL  (NF * W_STRIDE)               // 9728
#define W_TOT_ULL  (2 * W_BUF_ULL)               // 19456

template <int TPX, bool UP>
__global__ void __launch_bounds__(256, 1)
k_conv_mma(const float* __restrict__ xin, float* __restrict__ xout,
           const float* __restrict__ noise, const float* __restrict__ sn_ptr,
           const float* __restrict__ bias, int r) {
    constexpr int HW = TPX + 2;
    constexpr int X_PYS = HW * X_PXS;
    constexpr int NCB = TPX / 8;
    constexpr int E = 10 * HW * 8;
    constexpr int MAXE = (E + 255) / 256;

    extern __shared__ ull dyn[];
    ull* s_x = dyn + W_TOT_ULL;

    int b = blockIdx.z;
    int x0 = blockIdx.x * TPX, y0 = blockIdx.y * 8;
    int t = threadIdx.x;
    int warp = t >> 5, lane = t & 31;
    int co_w = warp * 16;
    int lq = lane >> 2;
    int lr = lane & 3;

    const size_t rr = (size_t)r * r;
    const int rin = r >> 1;
    const size_t rrin = (size_t)rin * rin;

    float acc[8][NCB][4];
    #pragma unroll
    for (int row = 0; row < 8; row++)
        #pragma unroll
        for (int cb = 0; cb < NCB; cb++)
            #pragma unroll
            for (int q = 0; q < 4; q++) acc[row][cb][q] = 0.f;

    // ---- weight async copy: one chunk (NF*36 uint4) -> buffer buf
    auto load_w = [&](int chunk, int buf) {
        const uint4* g4 = reinterpret_cast<const uint4*>(g_ws) +
                          (size_t)(b * 8 + chunk) * (NF * 36);
        ull* wb = dyn + buf * W_BUF_ULL;
        for (int e4 = t; e4 < NF * 36; e4 += 256) {
            int co = e4 / 36, rem = e4 - co * 36;
            cp16(&wb[co * W_STRIDE + rem * 2], g4 + e4);
        }
    };

    float pv0[MAXE], pv1[MAXE];
    // ---- x prefetch (gmem -> regs); UP: fused bilinear 2x upsample
    auto fetch_x = [&](int chunk) {
        #pragma unroll
        for (int i = 0; i < MAXE; i++) {
            int e = t + i * 256;
            float v0 = 0.f, v1 = 0.f;
            if (e < E) {
                int p = e & 7;
                int t2 = e >> 3;
                int px = t2 % HW, py = t2 / HW;
                int gy = y0 + py - 1, gx = x0 + px - 1;
                if (gy >= 0 && gy < r && gx >= 0 && gx < r) {
                    int ci = chunk * 16 + 2 * p;
                    if (UP) {
                        float fy = gy * 0.5f - 0.25f, fx = gx * 0.5f - 0.25f;
                        int iy0 = (int)floorf(fy), ix0 = (int)floorf(fx);
                        float ty = fy - iy0, tx = fx - ix0;
                        int y0c = max(iy0, 0), y1c = min(iy0 + 1, rin - 1);
                        int x0c = max(ix0, 0), x1c = min(ix0 + 1, rin - 1);
                        const float* p0 = xin + ((size_t)(b * NF + ci)) * rrin;
                        const float* p1 = p0 + rrin;
                        float a00 = p0[y0c * rin + x0c], a01 = p0[y0c * rin + x1c];
                        float a10 = p0[y1c * rin + x0c], a11 = p0[y1c * rin + x1c];
                        float b00 = p1[y0c * rin + x0c], b01 = p1[y0c * rin + x1c];
                        float b10 = p1[y1c * rin + x0c], b11 = p1[y1c * rin + x1c];
                        float u0 = a00 + tx * (a01 - a00);
                        float u1 = a10 + tx * (a11 - a10);
                        v0 = u0 + ty * (u1 - u0);
                        float w0 = b00 + tx * (b01 - b00);
                        float w1 = b10 + tx * (b11 - b10);
                        v1 = w0 + ty * (w1 - w0);
                    } else {
                        const float* pp = xin +
                            (((size_t)(b * NF + ci)) * r + gy) * r + gx;
                        v0 = pp[0];
                        v1 = pp[rr];
                    }
                }
            }
            pv0[i] = v0;
            pv1[i] = v1;
        }
    };
    auto store_x = [&]() {
        #pragma unroll
        for (int i = 0; i < MAXE; i++) {
            int e = t + i * 256;
            if (e < E) {
                int p = e & 7;
                int t2 = e >> 3;
                int px = t2 % HW, py = t2 / HW;
                unsigned int hi, lo;
                split2(pv0[i], pv1[i], hi, lo);
                s_x[py * X_PYS + px * X_PXS + p] = (ull)hi | ((ull)lo << 32);
            }
        }
    };

    // ---- prologue
    load_w(0, 0);
    cp_commit();
    fetch_x(0);
    store_x();
    cp_wait0();
    __syncthreads();

    #pragma unroll 1
    for (int chunk = 0; chunk < 8; chunk++) {
        if (chunk < 7) {
            load_w(chunk + 1, (chunk + 1) & 1);
            cp_commit();
            fetch_x(chunk + 1);
        }
        const ull* wbuf = dyn + (chunk & 1) * W_BUF_ULL;

        #pragma unroll 1
        for (int off = 0; off < 9; off++) {
            int ky = off / 3, kx = off - ky * 3;
            int wb = (co_w + lq) * W_STRIDE + off * 8 + lr;
            ull qa0 = wbuf[wb];
            ull qa1 = wbuf[wb + 8 * W_STRIDE];
            ull qa2 = wbuf[wb + 4];
            ull qa3 = wbuf[wb + 8 * W_STRIDE + 4];
            unsigned int ah[4], al[4];
            ah[0] = (unsigned int)qa0; al[0] = (unsigned int)(qa0 >> 32);
            ah[1] = (unsigned int)qa1; al[1] = (unsigned int)(qa1 >> 32);
            ah[2] = (unsigned int)qa2; al[2] = (unsigned int)(qa2 >> 32);
            ah[3] = (unsigned int)qa3; al[3] = (unsigned int)(qa3 >> 32);
            #pragma unroll
            for (int row = 0; row < 8; row++)
                #pragma unroll
                for (int cb = 0; cb < NCB; cb++) {
                    int xb = (ky + row) * X_PYS +
                             (lq + kx + cb * 8) * X_PXS + lr;
                    ull qb0 = s_x[xb];
                    ull qb1 = s_x[xb + 4];
                    unsigned int bh[2], bl[2];
                    bh[0] = (unsigned int)qb0; bl[0] = (unsigned int)(qb0 >> 32);
                    bh[1] = (unsigned int)qb1; bl[1] = (unsigned int)(qb1 >> 32);
                    mma16816(acc[row][cb], ah, bh);
                    mma16816(acc[row][cb], ah, bl);
                    mma16816(acc[row][cb], al, bh);
                }
        }
        __syncthreads();
        if (chunk < 7) {
            store_x();
            cp_wait0();
            __syncthreads();
        }
    }

    // ---- epilogue: noise + bias + leaky relu
    float sn = __ldg(sn_ptr);
    int co0 = co_w + lq, co1 = co0 + 8;
    float bb0 = bias[co0], bb1 = bias[co1];
    float* op0 = xout + ((size_t)(b * NF + co0)) * rr;
    float* op1 = xout + ((size_t)(b * NF + co1)) * rr;
    #pragma unroll
    for (int row = 0; row < 8; row++)
        #pragma unroll
        for (int cb = 0; cb < NCB; cb++) {
            int gy = y0 + row;
            int gx = x0 + cb * 8 + 2 * lr;
            const float* np = noise + ((size_t)b * r + gy) * r + gx;
            float n0 = sn * np[0], n1 = sn * np[1];
            float u0 = acc[row][cb][0] + n0 + bb0;
            float u1 = acc[row][cb][1] + n1 + bb0;
            float u2 = acc[row][cb][2] + n0 + bb1;
            float u3 = acc[row][cb][3] + n1 + bb1;
            u0 = u0 > 0.f ? u0 : 0.2f * u0;
            u1 = u1 > 0.f ? u1 : 0.2f * u1;
            u2 = u2 > 0.f ? u2 : 0.2f * u2;
            u3 = u3 > 0.f ? u3 : 0.2f * u3;
            *reinterpret_cast<float2*>(op0 + (size_t)gy * r + gx) = make_float2(u0, u1);
            *reinterpret_cast<float2*>(op1 + (size_t)gy * r + gx) = make_float2(u2, u3);
        }
}

// ---------------- ToRGB ------------------------------------------------------
__global__ void k_rgb(const float* __restrict__ xin, float* __restrict__ rgbout,
                      const float* __restrict__ rgb_w, int i, int r) {
    int b = blockIdx.y;
    __shared__ float wr[NF];
    if (threadIdx.x < NF) {
        const float cr = 0.08838834764831843f;  // 1/sqrt(128)
        wr[threadIdx.x] = rgb_w[i * NF + threadIdx.x] * cr * g_s[(i * BSZ + b) * NF + threadIdx.x];
    }
    __syncthreads();
    int p = blockIdx.x * blockDim.x + threadIdx.x;
    if (p >= r * r) return;
    const float* xp = xin + (size_t)b * NF * r * r + p;
    float acc = 0.f;
    #pragma unroll 4
    for (int ci = 0; ci < NF; ci++) acc += wr[ci] * xp[(size_t)ci * r * r];
    rgbout[(size_t)b * r * r + p] = acc;
}

// ---------------- final ------------------------------------------------------
__global__ void k_final(float* __restrict__ out) {
    int idx = blockIdx.x * blockDim.x + threadIdx.x;
    if (idx >= BSZ * IMG * IMG) return;
    int b = idx / (IMG * IMG);
    int rem = idx - b * (IMG * IMG);
    int y = rem >> 8, x = rem & 255;
    float sum = 0.f;
    int roff = 0;
    #pragma unroll
    for (int i = 0; i < 4; i++) {
        int r = 32 << i;
        const float* src = g_rgb + (size_t)BSZ * roff + (size_t)b * r * r;
        float sc = (float)r * (1.f / 256.f);
        float fy = (y + 0.5f) * sc - 0.5f;
        float fx = (x + 0.5f) * sc - 0.5f;
        int iy0 = (int)floorf(fy), ix0 = (int)floorf(fx);
        float ty = fy - iy0, tx = fx - ix0;
        int y0c = max(iy0, 0), y1c = min(iy0 + 1, r - 1);
        int x0c = max(ix0, 0), x1c = min(ix0 + 1, r - 1);
        float v00 = src[y0c * r + x0c], v01 = src[y0c * r + x1c];
        float v10 = src[y1c * r + x0c], v11 = src[y1c * r + x1c];
        float v0 = v00 + tx * (v01 - v00);
        float v1 = v10 + tx * (v11 - v10);
        sum += v0 + ty * (v1 - v0);
        roff += r * r;
    }
    out[idx] = sum * 0.5f + 0.5f;
}

// =============================================================================
static inline int conv_smem_bytes(int TPX) {
    int hw = TPX + 2;
    return (W_TOT_ULL + 10 * hw * X_PXS) * 8;
}

extern "C" void kernel_launch(void* const* d_in, const int* in_sizes, int n_in,
                              void* d_out, int out_size) {
    const float* w      = (const float*)d_in[0];
    const float* noise_in[4] = { (const float*)d_in[1], (const float*)d_in[2],
                                 (const float*)d_in[3], (const float*)d_in[4] };
    const float* ic     = (const float*)d_in[5];
    const float* tsw    = (const float*)d_in[6];
    const float* tsb    = (const float*)d_in[7];
    const float* conv_w = (const float*)d_in[8];
    const float* sn     = (const float*)d_in[9];
    const float* sbias  = (const float*)d_in[10];
    const float* rgb_w  = (const float*)d_in[11];
    float* out = (float*)d_out;

    float *xa, *xb, *rgb;
    cudaGetSymbolAddress((void**)&xa, g_xa);
    cudaGetSymbolAddress((void**)&xb, g_xb);
    cudaGetSymbolAddress((void**)&rgb, g_rgb);

    const int smem8  = conv_smem_bytes(8);
    const int smem16 = conv_smem_bytes(16);
    cudaFuncSetAttribute(k_conv_mma<8,  false>,
                         cudaFuncAttributeMaxDynamicSharedMemorySize, smem8);
    cudaFuncSetAttribute(k_conv_mma<16, false>,
                         cudaFuncAttributeMaxDynamicSharedMemorySize, smem16);
    cudaFuncSetAttribute(k_conv_mma<16, true>,
                         cudaFuncAttributeMaxDynamicSharedMemorySize, smem16);

    k_style<<<NB * BSZ, 128>>>(w, tsw, tsb);

    {
        int n = BSZ * NF * 32 * 32;
        k_init<<<(n + 255) / 256, 256>>>(ic, xa);
    }

    float* cur = xa;
    float* tmp = xb;
    int rgboff = 0;
    for (int i = 0; i < NB; i++) {
        int r = 32 << i;
        for (int j = 0; j < 2; j++) {
            k_modw<<<BSZ * NF, 256>>>(conv_w, i, j);
            const float* nz = noise_in[i] + (size_t)j * BSZ * r * r;
            const float* snp = sn + (i * 2 + j);
            const float* bp = sbias + (i * 2 + j) * NF;
            bool up = (i > 0 && j == 0);
            if (r == 32) {
                dim3 grid(r / 8, r / 8, BSZ);
                k_conv_mma<8, false><<<grid, 256, smem8>>>(cur, tmp, nz, snp, bp, r);
            } else {
                dim3 grid(r / 16, r / 8, BSZ);
                if (up)
                    k_conv_mma<16, true><<<grid, 256, smem16>>>(cur, tmp, nz, snp, bp, r);
                else
                    k_conv_mma<16, false><<<grid, 256, smem16>>>(cur, tmp, nz, snp, bp, r);
            }
            float* t2 = cur; cur = tmp; tmp = t2;
        }
        dim3 rg((r * r + 255) / 256, BSZ);
        k_rgb<<<rg, 256>>>(cur, rgb + (size_t)BSZ * rgboff, rgb_w, i, r);
        rgboff += r * r;
    }

    {
        int n = BSZ * IMG * IMG;
        k_final<<<(n + 255) / 256, 256>>>(out);
    }
}

// round 13
// speedup vs baseline: 1.1407x; 1.1407x over previous
#include <cuda_runtime.h>
#include <cuda_bf16.h>
#include <math.h>

#define NB   4
#define BSZ  8
#define NF   128
#define WDIM 512
#define IMG  256

// ---------------- scratch (static device globals; no allocation) -------------
__device__ float g_xa[BSZ * NF * IMG * IMG];
__device__ float g_xb[BSZ * NF * IMG * IMG];
__device__ float g_s[NB * BSZ * NF];
__device__ float g_rgb[BSZ * (32*32 + 64*64 + 128*128 + 256*256)];
// pre-split modulated weights, MMA-pair layout: [b][chunk(ci/16)][co][tap k][ci2 pair]
__device__ unsigned int g_wsh[BSZ * 8 * NF * 72];
__device__ unsigned int g_wsl[BSZ * 8 * NF * 72];

// ---------------- helpers ----------------------------------------------------
__device__ __forceinline__ void split2(float v0, float v1,
                                       unsigned int& hi, unsigned int& lo) {
    __nv_bfloat16 h0 = __float2bfloat16(v0);
    __nv_bfloat16 h1 = __float2bfloat16(v1);
    float r0 = v0 - __bfloat162float(h0);
    float r1 = v1 - __bfloat162float(h1);
    __nv_bfloat16 l0 = __float2bfloat16(r0);
    __nv_bfloat16 l1 = __float2bfloat16(r1);
    hi = (unsigned int)__bfloat16_as_ushort(h0) |
         ((unsigned int)__bfloat16_as_ushort(h1) << 16);
    lo = (unsigned int)__bfloat16_as_ushort(l0) |
         ((unsigned int)__bfloat16_as_ushort(l1) << 16);
}

__device__ __forceinline__ void mma16816(float* d, const unsigned int* a,
                                         const unsigned int* b) {
    asm volatile(
        "mma.sync.aligned.m16n8k16.row.col.f32.bf16.bf16.f32 "
        "{%0,%1,%2,%3}, {%4,%5,%6,%7}, {%8,%9}, {%0,%1,%2,%3};\n"
        : "+f"(d[0]), "+f"(d[1]), "+f"(d[2]), "+f"(d[3])
        : "r"(a[0]), "r"(a[1]), "r"(a[2]), "r"(a[3]), "r"(b[0]), "r"(b[1]));
}

__device__ __forceinline__ void cp16(unsigned int* smem_dst, const void* gsrc) {
    unsigned int sa = (unsigned int)__cvta_generic_to_shared(smem_dst);
    asm volatile("cp.async.cg.shared.global [%0], [%1], 16;\n"
                 :: "r"(sa), "l"(gsrc));
}
__device__ __forceinline__ void cp_commit() {
    asm volatile("cp.async.commit_group;\n");
}
__device__ __forceinline__ void cp_wait0() {
    asm volatile("cp.async.wait_group 0;\n");
}

// ---------------- styles -----------------------------------------------------
__global__ void k_style(const float* __restrict__ w, const float* __restrict__ tsw,
                        const float* __restrict__ tsb) {
    int i = blockIdx.x / BSZ, b = blockIdx.x % BSZ;
    int c = threadIdx.x;
    __shared__ float sw[WDIM];
    for (int d = threadIdx.x; d < WDIM; d += blockDim.x)
        sw[d] = w[(i * BSZ + b) * WDIM + d];
    __syncthreads();
    const float* tw = tsw + (i * NF + c) * WDIM;
    float acc = 0.f;
    #pragma unroll 4
    for (int d = 0; d < WDIM; d++) acc += sw[d] * tw[d];
    const float cl = 0.044194173824159216f;   // 1/sqrt(512)
    g_s[(i * BSZ + b) * NF + c] = acc * cl + tsb[i * NF + c];
}

// ---- modulated + demodulated weights -> pre-split bf16 hi/lo, pair layout ---
__global__ void k_modw(const float* __restrict__ conv_w, int i, int j) {
    int b = blockIdx.x / NF, co = blockIdx.x % NF;
    const float* wsrc = conv_w + (((size_t)(i * 2 + j) * NF + co) * NF) * 9;
    const float* s = g_s + (i * BSZ + b) * NF;
    const float c = 0.029462782549439483f;    // 1/sqrt(128*9)
    __shared__ float buf[NF * 9];
    __shared__ float red[32];
    float ss = 0.f;
    for (int t = threadIdx.x; t < NF * 9; t += blockDim.x) {
        float v = wsrc[t] * c * s[t / 9];
        buf[t] = v;
        ss += v * v;
    }
    for (int o = 16; o; o >>= 1) ss += __shfl_xor_sync(0xffffffffu, ss, o);
    if ((threadIdx.x & 31) == 0) red[threadIdx.x >> 5] = ss;
    __syncthreads();
    if (threadIdx.x < 32) {
        float v = (threadIdx.x < (blockDim.x >> 5)) ? red[threadIdx.x] : 0.f;
        for (int o = 16; o; o >>= 1) v += __shfl_xor_sync(0xffffffffu, v, o);
        if (threadIdx.x == 0) red[0] = v;
    }
    __syncthreads();
    float dem = rsqrtf(red[0] + 1e-8f);
    for (int e = threadIdx.x; e < 576; e += blockDim.x) {
        int ci2g = e / 9, k = e - ci2g * 9;
        int ci = ci2g * 2;
        float v0 = buf[ci * 9 + k] * dem;
        float v1 = buf[ci * 9 + 9 + k] * dem;
        unsigned int hi, lo;
        split2(v0, v1, hi, lo);
        int chunk = ci2g >> 3, p = ci2g & 7;
        size_t idx = (((size_t)(b * 8 + chunk) * NF + co) * 9 + k) * 8 + p;
        g_wsh[idx] = hi;
        g_wsl[idx] = lo;
    }
}

// ---------------- initial constant -------------------------------------------
__global__ void k_init(const float* __restrict__ ic, float* __restrict__ x) {
    int idx = blockIdx.x * blockDim.x + threadIdx.x;
    if (idx >= BSZ * NF * 32 * 32) return;
    int per = NF * 32 * 32;
    float v = ic[idx % per];
    x[idx] = v > 0.f ? v : 0.f;
}

// ---------------- tensor-core modulated conv3x3, pipelined (R9 config) -------
// CTA: 128 co x (TPX x 8) px. 256 threads = 8 warps; warp = 16co x all px.
// Separate hi/lo uint smem (LDS.32 fragments), double-buffered cp.async
// weights, register-prefetched x tile; UP fuses bilinear 2x upsample.
#define W_STRIDE 76
#define X_PXS    12
#define W_BUF_U32 (2 * NF * W_STRIDE)            // hi+lo for one chunk: 19456
#define W_TOTAL_U32 (2 * W_BUF_U32)              // two buffers: 38912

template <int TPX, bool UP>
__global__ void __launch_bounds__(256, 1)
k_conv_mma(const float* __restrict__ xin, float* __restrict__ xout,
           const float* __restrict__ noise, const float* __restrict__ sn_ptr,
           const float* __restrict__ bias, int r) {
    constexpr int HW = TPX + 2;                  // halo width
    constexpr int X_PYS = HW * X_PXS;
    constexpr int NCB = TPX / 8;                 // 8-px column blocks (1 or 2)
    constexpr int E = 10 * HW * 8;               // x-tile entries (pairs)
    constexpr int MAXE = (E + 255) / 256;
    constexpr int XH_OFF = W_TOTAL_U32;
    constexpr int XL_OFF = XH_OFF + 10 * X_PYS;

    extern __shared__ unsigned int dyn[];

    int b = blockIdx.z;
    int x0 = blockIdx.x * TPX, y0 = blockIdx.y * 8;
    int t = threadIdx.x;
    int warp = t >> 5, lane = t & 31;
    int co_w = warp * 16;
    int lq = lane >> 2;
    int lr = lane & 3;

    const size_t rr = (size_t)r * r;
    const int rin = r >> 1;
    const size_t rrin = (size_t)rin * rin;

    float acc[8][NCB][4];
    #pragma unroll
    for (int row = 0; row < 8; row++)
        #pragma unroll
        for (int cb = 0; cb < NCB; cb++)
            #pragma unroll
            for (int q = 0; q < 4; q++) acc[row][cb][q] = 0.f;

    // ---- weight async copy helper (restride 72 -> 76), one chunk -> buf
    auto load_w = [&](int chunk, int buf) {
        size_t base4 = (size_t)(b * 8 + chunk) * (NF * 18);
        const uint4* gh = reinterpret_cast<const uint4*>(g_wsh) + base4;
        const uint4* gl = reinterpret_cast<const uint4*>(g_wsl) + base4;
        unsigned int* wh = dyn + buf * W_BUF_U32;
        unsigned int* wl = wh + NF * W_STRIDE;
        for (int e4 = t; e4 < NF * 18; e4 += 256) {
            int co = e4 / 18, rem = e4 - co * 18;
            cp16(&wh[co * W_STRIDE + rem * 4], gh + e4);
            cp16(&wl[co * W_STRIDE + rem * 4], gl + e4);
        }
    };

    float pv0[MAXE], pv1[MAXE];
    // ---- x prefetch (gmem -> regs); UP: fused bilinear 2x upsample
    auto fetch_x = [&](int chunk) {
        #pragma unroll
        for (int i = 0; i < MAXE; i++) {
            int e = t + i * 256;
            float v0 = 0.f, v1 = 0.f;
            if (e < E) {
                int p = e & 7;
                int t2 = e >> 3;
                int px = t2 % HW, py = t2 / HW;
                int gy = y0 + py - 1, gx = x0 + px - 1;
                if (gy >= 0 && gy < r && gx >= 0 && gx < r) {
                    int ci = chunk * 16 + 2 * p;
                    if (UP) {
                        float fy = gy * 0.5f - 0.25f, fx = gx * 0.5f - 0.25f;
                        int iy0 = (int)floorf(fy), ix0 = (int)floorf(fx);
                        float ty = fy - iy0, tx = fx - ix0;
                        int y0c = max(iy0, 0), y1c = min(iy0 + 1, rin - 1);
                        int x0c = max(ix0, 0), x1c = min(ix0 + 1, rin - 1);
                        const float* p0 = xin + ((size_t)(b * NF + ci)) * rrin;
                        const float* p1 = p0 + rrin;
                        float a00 = p0[y0c * rin + x0c], a01 = p0[y0c * rin + x1c];
                        float a10 = p0[y1c * rin + x0c], a11 = p0[y1c * rin + x1c];
                        float b00 = p1[y0c * rin + x0c], b01 = p1[y0c * rin + x1c];
                        float b10 = p1[y1c * rin + x0c], b11 = p1[y1c * rin + x1c];
                        float u0 = a00 + tx * (a01 - a00);
                        float u1 = a10 + tx * (a11 - a10);
                        v0 = u0 + ty * (u1 - u0);
                        float w0 = b00 + tx * (b01 - b00);
                        float w1 = b10 + tx * (b11 - b10);
                        v1 = w0 + ty * (w1 - w0);
                    } else {
                        const float* pp = xin +
                            (((size_t)(b * NF + ci)) * r + gy) * r + gx;
                        v0 = pp[0];
                        v1 = pp[rr];
                    }
                }
            }
            pv0[i] = v0;
            pv1[i] = v1;
        }
    };
    // ---- split + store prefetched x regs to smem
    auto store_x = [&]() {
        #pragma unroll
        for (int i = 0; i < MAXE; i++) {
            int e = t + i * 256;
            if (e < E) {
                int p = e & 7;
                int t2 = e >> 3;
                int px = t2 % HW, py = t2 / HW;
                unsigned int hi, lo;
                split2(pv0[i], pv1[i], hi, lo);
                int off = py * X_PYS + px * X_PXS + p;
                dyn[XH_OFF + off] = hi;
                dyn[XL_OFF + off] = lo;
            }
        }
    };

    // ---- prologue: chunk 0
    load_w(0, 0);
    cp_commit();
    fetch_x(0);
    store_x();
    cp_wait0();
    __syncthreads();

    #pragma unroll 1
    for (int chunk = 0; chunk < 8; chunk++) {
        if (chunk < 7) {
            load_w(chunk + 1, (chunk + 1) & 1);
            cp_commit();
            fetch_x(chunk + 1);
        }
        const unsigned int* wh = dyn + (chunk & 1) * W_BUF_U32;
        const unsigned int* wl = wh + NF * W_STRIDE;

        #pragma unroll 1
        for (int off = 0; off < 9; off++) {
            int ky = off / 3, kx = off - ky * 3;
            int wbase = (co_w + lq) * W_STRIDE + off * 8 + lr;
            unsigned int ah[4], al[4];
            ah[0] = wh[wbase];
            ah[1] = wh[wbase + 8 * W_STRIDE];
            ah[2] = wh[wbase + 4];
            ah[3] = wh[wbase + 8 * W_STRIDE + 4];
            al[0] = wl[wbase];
            al[1] = wl[wbase + 8 * W_STRIDE];
            al[2] = wl[wbase + 4];
            al[3] = wl[wbase + 8 * W_STRIDE + 4];
            int xbase = ky * X_PYS + (lq + kx) * X_PXS + lr;
            #pragma unroll
            for (int row = 0; row < 8; row++)
                #pragma unroll
                for (int cb = 0; cb < NCB; cb++) {
                    int xb = xbase + row * X_PYS + cb * (8 * X_PXS);
                    unsigned int bh[2], bl[2];
                    bh[0] = dyn[XH_OFF + xb];
                    bh[1] = dyn[XH_OFF + xb + 4];
                    bl[0] = dyn[XL_OFF + xb];
                    bl[1] = dyn[XL_OFF + xb + 4];
                    mma16816(acc[row][cb], ah, bh);
                    mma16816(acc[row][cb], ah, bl);
                    mma16816(acc[row][cb], al, bh);
                }
        }
        __syncthreads();
        if (chunk < 7) {
            store_x();
            cp_wait0();
            __syncthreads();
        }
    }

    // ---- epilogue: noise + bias + leaky relu
    float sn = __ldg(sn_ptr);
    int co0 = co_w + lq, co1 = co0 + 8;
    float bb0 = bias[co0], bb1 = bias[co1];
    float* op0 = xout + ((size_t)(b * NF + co0)) * rr;
    float* op1 = xout + ((size_t)(b * NF + co1)) * rr;
    #pragma unroll
    for (int row = 0; row < 8; row++)
        #pragma unroll
        for (int cb = 0; cb < NCB; cb++) {
            int gy = y0 + row;
            int gx = x0 + cb * 8 + 2 * lr;
            const float* np = noise + ((size_t)b * r + gy) * r + gx;
            float n0 = sn * np[0], n1 = sn * np[1];
            float u0 = acc[row][cb][0] + n0 + bb0;
            float u1 = acc[row][cb][1] + n1 + bb0;
            float u2 = acc[row][cb][2] + n0 + bb1;
            float u3 = acc[row][cb][3] + n1 + bb1;
            u0 = u0 > 0.f ? u0 : 0.2f * u0;
            u1 = u1 > 0.f ? u1 : 0.2f * u1;
            u2 = u2 > 0.f ? u2 : 0.2f * u2;
            u3 = u3 > 0.f ? u3 : 0.2f * u3;
            *reinterpret_cast<float2*>(op0 + (size_t)gy * r + gx) = make_float2(u0, u1);
            *reinterpret_cast<float2*>(op1 + (size_t)gy * r + gx) = make_float2(u2, u3);
        }
}

// ---------------- ToRGB ------------------------------------------------------
__global__ void k_rgb(const float* __restrict__ xin, float* __restrict__ rgbout,
                      const float* __restrict__ rgb_w, int i, int r) {
    int b = blockIdx.y;
    __shared__ float wr[NF];
    if (threadIdx.x < NF) {
        const float cr = 0.08838834764831843f;  // 1/sqrt(128)
        wr[threadIdx.x] = rgb_w[i * NF + threadIdx.x] * cr * g_s[(i * BSZ + b) * NF + threadIdx.x];
    }
    __syncthreads();
    int p = blockIdx.x * blockDim.x + threadIdx.x;
    if (p >= r * r) return;
    const float* xp = xin + (size_t)b * NF * r * r + p;
    float acc = 0.f;
    #pragma unroll 4
    for (int ci = 0; ci < NF; ci++) acc += wr[ci] * xp[(size_t)ci * r * r];
    rgbout[(size_t)b * r * r + p] = acc;
}

// ---------------- final ------------------------------------------------------
__global__ void k_final(float* __restrict__ out) {
    int idx = blockIdx.x * blockDim.x + threadIdx.x;
    if (idx >= BSZ * IMG * IMG) return;
    int b = idx / (IMG * IMG);
    int rem = idx - b * (IMG * IMG);
    int y = rem >> 8, x = rem & 255;
    float sum = 0.f;
    int roff = 0;
    #pragma unroll
    for (int i = 0; i < 4; i++) {
        int r = 32 << i;
        const float* src = g_rgb + (size_t)BSZ * roff + (size_t)b * r * r;
        float sc = (float)r * (1.f / 256.f);
        float fy = (y + 0.5f) * sc - 0.5f;
        float fx = (x + 0.5f) * sc - 0.5f;
        int iy0 = (int)floorf(fy), ix0 = (int)floorf(fx);
        float ty = fy - iy0, tx = fx - ix0;
        int y0c = max(iy0, 0), y1c = min(iy0 + 1, r - 1);
        int x0c = max(ix0, 0), x1c = min(ix0 + 1, r - 1);
        float v00 = src[y0c * r + x0c], v01 = src[y0c * r + x1c];
        float v10 = src[y1c * r + x0c], v11 = src[y1c * r + x1c];
        float v0 = v00 + tx * (v01 - v00);
        float v1 = v10 + tx * (v11 - v10);
        sum += v0 + ty * (v1 - v0);
        roff += r * r;
    }
    out[idx] = sum * 0.5f + 0.5f;
}

// =============================================================================
static inline int conv_smem_bytes(int TPX) {
    int hw = TPX + 2;
    int x_u32 = 2 * 10 * hw * X_PXS;
    return (W_TOTAL_U32 + x_u32) * 4;
}

extern "C" void kernel_launch(void* const* d_in, const int* in_sizes, int n_in,
                              void* d_out, int out_size) {
    const float* w      = (const float*)d_in[0];
    const float* noise_in[4] = { (const float*)d_in[1], (const float*)d_in[2],
                                 (const float*)d_in[3], (const float*)d_in[4] };
    const float* ic     = (const float*)d_in[5];
    const float* tsw    = (const float*)d_in[6];
    const float* tsb    = (const float*)d_in[7];
    const float* conv_w = (const float*)d_in[8];
    const float* sn     = (const float*)d_in[9];
    const float* sbias  = (const float*)d_in[10];
    const float* rgb_w  = (const float*)d_in[11];
    float* out = (float*)d_out;

    float *xa, *xb, *rgb;
    cudaGetSymbolAddress((void**)&xa, g_xa);
    cudaGetSymbolAddress((void**)&xb, g_xb);
    cudaGetSymbolAddress((void**)&rgb, g_rgb);

    const int smem8  = conv_smem_bytes(8);
    const int smem16 = conv_smem_bytes(16);
    cudaFuncSetAttribute(k_conv_mma<8,  false>,
                         cudaFuncAttributeMaxDynamicSharedMemorySize, smem8);
    cudaFuncSetAttribute(k_conv_mma<16, false>,
                         cudaFuncAttributeMaxDynamicSharedMemorySize, smem16);
    cudaFuncSetAttribute(k_conv_mma<16, true>,
                         cudaFuncAttributeMaxDynamicSharedMemorySize, smem16);

    k_style<<<NB * BSZ, 128>>>(w, tsw, tsb);

    {
        int n = BSZ * NF * 32 * 32;
        k_init<<<(n + 255) / 256, 256>>>(ic, xa);
    }

    float* cur = xa;
    float* tmp = xb;
    int rgboff = 0;
    for (int i = 0; i < NB; i++) {
        int r = 32 << i;
        for (int j = 0; j < 2; j++) {
            k_modw<<<BSZ * NF, 256>>>(conv_w, i, j);
            const float* nz = noise_in[i] + (size_t)j * BSZ * r * r;
            const float* snp = sn + (i * 2 + j);
            const float* bp = sbias + (i * 2 + j) * NF;
            bool up = (i > 0 && j == 0);
            if (r == 32) {
                dim3 grid(r / 8, r / 8, BSZ);
                k_conv_mma<8, false><<<grid, 256, smem8>>>(cur, tmp, nz, snp, bp, r);
            } else {
                dim3 grid(r / 16, r / 8, BSZ);
                if (up)
                    k_conv_mma<16, true><<<grid, 256, smem16>>>(cur, tmp, nz, snp, bp, r);
                else
                    k_conv_mma<16, false><<<grid, 256, smem16>>>(cur, tmp, nz, snp, bp, r);
            }
            float* t2 = cur; cur = tmp; tmp = t2;
        }
        dim3 rg((r * r + 255) / 256, BSZ);
        k_rgb<<<rg, 256>>>(cur, rgb + (size_t)BSZ * rgboff, rgb_w, i, r);
        rgboff += r * r;
    }

    {
        int n = BSZ * IMG * IMG;
        k_final<<<(n + 255) / 256, 256>>>(out);
    }
}

// round 15
// speedup vs baseline: 1.1831x; 1.0371x over previous
#include <cuda_runtime.h>
#include <cuda_bf16.h>
#include <math.h>

#define NB   4
#define BSZ  8
#define NF   128
#define WDIM 512
#define IMG  256

// ---------------- scratch (static device globals; no allocation) -------------
__device__ float g_xa[BSZ * NF * IMG * IMG];
__device__ float g_xb[BSZ * NF * IMG * IMG];
__device__ float g_s[NB * BSZ * NF];
__device__ float g_rgb[BSZ * (32*32 + 64*64 + 128*128 + 256*256)];
// pre-split modulated weights, MMA-pair layout: [b][chunk(ci/16)][co][tap k][ci2 pair]
__device__ unsigned int g_wsh[BSZ * 8 * NF * 72];
__device__ unsigned int g_wsl[BSZ * 8 * NF * 72];

// ---------------- helpers ----------------------------------------------------
__device__ __forceinline__ void split2(float v0, float v1,
                                       unsigned int& hi, unsigned int& lo) {
    __nv_bfloat16 h0 = __float2bfloat16(v0);
    __nv_bfloat16 h1 = __float2bfloat16(v1);
    float r0 = v0 - __bfloat162float(h0);
    float r1 = v1 - __bfloat162float(h1);
    __nv_bfloat16 l0 = __float2bfloat16(r0);
    __nv_bfloat16 l1 = __float2bfloat16(r1);
    hi = (unsigned int)__bfloat16_as_ushort(h0) |
         ((unsigned int)__bfloat16_as_ushort(h1) << 16);
    lo = (unsigned int)__bfloat16_as_ushort(l0) |
         ((unsigned int)__bfloat16_as_ushort(l1) << 16);
}

__device__ __forceinline__ void mma16816(float* d, const unsigned int* a,
                                         const unsigned int* b) {
    asm volatile(
        "mma.sync.aligned.m16n8k16.row.col.f32.bf16.bf16.f32 "
        "{%0,%1,%2,%3}, {%4,%5,%6,%7}, {%8,%9}, {%0,%1,%2,%3};\n"
        : "+f"(d[0]), "+f"(d[1]), "+f"(d[2]), "+f"(d[3])
        : "r"(a[0]), "r"(a[1]), "r"(a[2]), "r"(a[3]), "r"(b[0]), "r"(b[1]));
}

__device__ __forceinline__ void cp16(unsigned int* smem_dst, const void* gsrc) {
    unsigned int sa = (unsigned int)__cvta_generic_to_shared(smem_dst);
    asm volatile("cp.async.cg.shared.global [%0], [%1], 16;\n"
                 :: "r"(sa), "l"(gsrc));
}
__device__ __forceinline__ void cp_commit() {
    asm volatile("cp.async.commit_group;\n");
}
__device__ __forceinline__ void cp_wait0() {
    asm volatile("cp.async.wait_group 0;\n");
}

// ---------------- styles -----------------------------------------------------
__global__ void k_style(const float* __restrict__ w, const float* __restrict__ tsw,
                        const float* __restrict__ tsb) {
    int i = blockIdx.x / BSZ, b = blockIdx.x % BSZ;
    int c = threadIdx.x;
    __shared__ float sw[WDIM];
    for (int d = threadIdx.x; d < WDIM; d += blockDim.x)
        sw[d] = w[(i * BSZ + b) * WDIM + d];
    __syncthreads();
    const float* tw = tsw + (i * NF + c) * WDIM;
    float acc = 0.f;
    #pragma unroll 4
    for (int d = 0; d < WDIM; d++) acc += sw[d] * tw[d];
    const float cl = 0.044194173824159216f;   // 1/sqrt(512)
    g_s[(i * BSZ + b) * NF + c] = acc * cl + tsb[i * NF + c];
}

// ---- modulated + demodulated weights -> pre-split bf16 hi/lo, pair layout ---
__global__ void k_modw(const float* __restrict__ conv_w, int i, int j) {
    int b = blockIdx.x / NF, co = blockIdx.x % NF;
    const float* wsrc = conv_w + (((size_t)(i * 2 + j) * NF + co) * NF) * 9;
    const float* s = g_s + (i * BSZ + b) * NF;
    const float c = 0.029462782549439483f;    // 1/sqrt(128*9)
    __shared__ float buf[NF * 9];
    __shared__ float red[32];
    float ss = 0.f;
    for (int t = threadIdx.x; t < NF * 9; t += blockDim.x) {
        float v = wsrc[t] * c * s[t / 9];
        buf[t] = v;
        ss += v * v;
    }
    for (int o = 16; o; o >>= 1) ss += __shfl_xor_sync(0xffffffffu, ss, o);
    if ((threadIdx.x & 31) == 0) red[threadIdx.x >> 5] = ss;
    __syncthreads();
    if (threadIdx.x < 32) {
        float v = (threadIdx.x < (blockDim.x >> 5)) ? red[threadIdx.x] : 0.f;
        for (int o = 16; o; o >>= 1) v += __shfl_xor_sync(0xffffffffu, v, o);
        if (threadIdx.x == 0) red[0] = v;
    }
    __syncthreads();
    float dem = rsqrtf(red[0] + 1e-8f);
    for (int e = threadIdx.x; e < 576; e += blockDim.x) {
        int ci2g = e / 9, k = e - ci2g * 9;
        int ci = ci2g * 2;
        float v0 = buf[ci * 9 + k] * dem;
        float v1 = buf[ci * 9 + 9 + k] * dem;
        unsigned int hi, lo;
        split2(v0, v1, hi, lo);
        int chunk = ci2g >> 3, p = ci2g & 7;
        size_t idx = (((size_t)(b * 8 + chunk) * NF + co) * 9 + k) * 8 + p;
        g_wsh[idx] = hi;
        g_wsl[idx] = lo;
    }
}

// ---------------- initial constant -------------------------------------------
__global__ void k_init(const float* __restrict__ ic, float* __restrict__ x) {
    int idx = blockIdx.x * blockDim.x + threadIdx.x;
    if (idx >= BSZ * NF * 32 * 32) return;
    int per = NF * 32 * 32;
    float v = ic[idx % per];
    x[idx] = v > 0.f ? v : 0.f;
}

// ---------------- bilinear 2x upsample ---------------------------------------
__global__ void k_up(const float* __restrict__ in, float* __restrict__ out, int rin) {
    int rout = rin * 2;
    int idx = blockIdx.x * blockDim.x + threadIdx.x;
    int total = BSZ * NF * rout * rout;
    if (idx >= total) return;
    int x = idx % rout;
    int t2 = idx / rout;
    int y = t2 % rout;
    int bc = t2 / rout;
    float fy = y * 0.5f - 0.25f, fx = x * 0.5f - 0.25f;
    int iy0 = (int)floorf(fy), ix0 = (int)floorf(fx);
    float ty = fy - iy0, tx = fx - ix0;
    int y0c = max(iy0, 0), y1c = min(iy0 + 1, rin - 1);
    int x0c = max(ix0, 0), x1c = min(ix0 + 1, rin - 1);
    const float* p = in + (size_t)bc * rin * rin;
    float v00 = p[y0c * rin + x0c], v01 = p[y0c * rin + x1c];
    float v10 = p[y1c * rin + x0c], v11 = p[y1c * rin + x1c];
    float v0 = v00 + tx * (v01 - v00);
    float v1 = v10 + tx * (v11 - v10);
    out[idx] = v0 + ty * (v1 - v0);
}

// ---------------- tensor-core modulated conv3x3, row-slide mainloop ----------
// CTA: 128 co x (TPX x 8) px. 256 threads = 8 warps; warp = 16co x all px.
// Per chunk: preload all 9 taps' A-fragments into registers (72 LDS), then
// sweep the 10 smem x-rows once; each row's 6 B positions (12 LDS/cb) feed the
// 3 acc-rows (ky=0..2) that use that row. B-LDS drops 576->240 per warp-chunk
// (TPX=16), flipping the loop from crossbar-bound to tensor-bound.
// Per-accumulator accumulation order is unchanged (ky-major, kx-minor,
// hh/hl/lh triple) -> bitwise-identical results to R9.
#define W_STRIDE 76
#define X_PXS    12
#define W_BUF_U32 (2 * NF * W_STRIDE)            // hi+lo for one chunk: 19456
#define W_TOTAL_U32 (2 * W_BUF_U32)              // two buffers: 38912

template <int TPX>
__global__ void __launch_bounds__(256, 1)
k_conv_mma(const float* __restrict__ xin, float* __restrict__ xout,
           const float* __restrict__ noise, const float* __restrict__ sn_ptr,
           const float* __restrict__ bias, int r) {
    constexpr int HW = TPX + 2;                  // halo width
    constexpr int X_PYS = HW * X_PXS;
    constexpr int NCB = TPX / 8;                 // 8-px column blocks (1 or 2)
    constexpr int E = 10 * HW * 8;               // x-tile entries (pairs)
    constexpr int MAXE = (E + 255) / 256;
    constexpr int XH_OFF = W_TOTAL_U32;
    constexpr int XL_OFF = XH_OFF + 10 * X_PYS;

    extern __shared__ unsigned int dyn[];

    int b = blockIdx.z;
    int x0 = blockIdx.x * TPX, y0 = blockIdx.y * 8;
    int t = threadIdx.x;
    int warp = t >> 5, lane = t & 31;
    int co_w = warp * 16;
    int lq = lane >> 2;
    int lr = lane & 3;

    const size_t rr = (size_t)r * r;

    float acc[8][NCB][4];
    #pragma unroll
    for (int row = 0; row < 8; row++)
        #pragma unroll
        for (int cb = 0; cb < NCB; cb++)
            #pragma unroll
            for (int q = 0; q < 4; q++) acc[row][cb][q] = 0.f;

    // ---- weight async copy helper (restride 72 -> 76), one chunk -> buf
    auto load_w = [&](int chunk, int buf) {
        size_t base4 = (size_t)(b * 8 + chunk) * (NF * 18);
        const uint4* gh = reinterpret_cast<const uint4*>(g_wsh) + base4;
        const uint4* gl = reinterpret_cast<const uint4*>(g_wsl) + base4;
        unsigned int* wh = dyn + buf * W_BUF_U32;
        unsigned int* wl = wh + NF * W_STRIDE;
        for (int e4 = t; e4 < NF * 18; e4 += 256) {
            int co = e4 / 18, rem = e4 - co * 18;
            cp16(&wh[co * W_STRIDE + rem * 4], gh + e4);
            cp16(&wl[co * W_STRIDE + rem * 4], gl + e4);
        }
    };

    float pv0[MAXE], pv1[MAXE];
    // ---- x prefetch (gmem -> regs) for a chunk
    auto fetch_x = [&](int chunk) {
        #pragma unroll
        for (int i = 0; i < MAXE; i++) {
            int e = t + i * 256;
            float v0 = 0.f, v1 = 0.f;
            if (e < E) {
                int p = e & 7;
                int t2 = e >> 3;
                int px = t2 % HW, py = t2 / HW;
                int gy = y0 + py - 1, gx = x0 + px - 1;
                if (gy >= 0 && gy < r && gx >= 0 && gx < r) {
                    const float* pp = xin +
                        (((size_t)(b * NF + chunk * 16 + 2 * p)) * r + gy) * r + gx;
                    v0 = pp[0];
                    v1 = pp[rr];
                }
            }
            pv0[i] = v0;
            pv1[i] = v1;
        }
    };
    // ---- split + store prefetched x regs to smem
    auto store_x = [&]() {
        #pragma unroll
        for (int i = 0; i < MAXE; i++) {
            int e = t + i * 256;
            if (e < E) {
                int p = e & 7;
                int t2 = e >> 3;
                int px = t2 % HW, py = t2 / HW;
                unsigned int hi, lo;
                split2(pv0[i], pv1[i], hi, lo);
                int off = py * X_PYS + px * X_PXS + p;
                dyn[XH_OFF + off] = hi;
                dyn[XL_OFF + off] = lo;
            }
        }
    };

    // ---- prologue: chunk 0
    load_w(0, 0);
    cp_commit();
    fetch_x(0);
    store_x();
    cp_wait0();
    __syncthreads();

    #pragma unroll 1
    for (int chunk = 0; chunk < 8; chunk++) {
        if (chunk < 7) {
            load_w(chunk + 1, (chunk + 1) & 1);
            cp_commit();
            fetch_x(chunk + 1);
        }
        const unsigned int* wh = dyn + (chunk & 1) * W_BUF_U32;
        const unsigned int* wl = wh + NF * W_STRIDE;

        // ---- preload all 9 taps' A-fragments (held in regs for the chunk)
        unsigned int ah[9][4], al[9][4];
        #pragma unroll
        for (int off = 0; off < 9; off++) {
            int wbase = (co_w + lq) * W_STRIDE + off * 8 + lr;
            ah[off][0] = wh[wbase];
            ah[off][1] = wh[wbase + 8 * W_STRIDE];
            ah[off][2] = wh[wbase + 4];
            ah[off][3] = wh[wbase + 8 * W_STRIDE + 4];
            al[off][0] = wl[wbase];
            al[off][1] = wl[wbase + 8 * W_STRIDE];
            al[off][2] = wl[wbase + 4];
            al[off][3] = wl[wbase + 8 * W_STRIDE + 4];
        }

        // ---- row-slide sweep over the 10 smem x-rows
        #pragma unroll
        for (int s = 0; s < 10; s++) {
            #pragma unroll
            for (int cb = 0; cb < NCB; cb++) {
                int base = s * X_PYS + (lq + cb * 8) * X_PXS + lr;
                unsigned int bh0[3], bh1[3], bl0[3], bl1[3];
                #pragma unroll
                for (int kx = 0; kx < 3; kx++) {
                    bh0[kx] = dyn[XH_OFF + base + kx * X_PXS];
                    bh1[kx] = dyn[XH_OFF + base + kx * X_PXS + 4];
                    bl0[kx] = dyn[XL_OFF + base + kx * X_PXS];
                    bl1[kx] = dyn[XL_OFF + base + kx * X_PXS + 4];
                }
                #pragma unroll
                for (int ky = 0; ky < 3; ky++) {
                    int row = s - ky;
                    if (row >= 0 && row < 8) {
                        #pragma unroll
                        for (int kx = 0; kx < 3; kx++) {
                            unsigned int bh[2] = { bh0[kx], bh1[kx] };
                            unsigned int bl[2] = { bl0[kx], bl1[kx] };
                            int off = ky * 3 + kx;
                            mma16816(acc[row][cb], ah[off], bh);
                            mma16816(acc[row][cb], ah[off], bl);
                            mma16816(acc[row][cb], al[off], bh);
                        }
                    }
                }
            }
        }
        __syncthreads();
        if (chunk < 7) {
            store_x();
            cp_wait0();
            __syncthreads();
        }
    }

    // ---- epilogue: noise + bias + leaky relu
    float sn = __ldg(sn_ptr);
    int co0 = co_w + lq, co1 = co0 + 8;
    float bb0 = bias[co0], bb1 = bias[co1];
    float* op0 = xout + ((size_t)(b * NF + co0)) * rr;
    float* op1 = xout + ((size_t)(b * NF + co1)) * rr;
    #pragma unroll
    for (int row = 0; row < 8; row++)
        #pragma unroll
        for (int cb = 0; cb < NCB; cb++) {
            int gy = y0 + row;
            int gx = x0 + cb * 8 + 2 * lr;
            const float* np = noise + ((size_t)b * r + gy) * r + gx;
            float n0 = sn * np[0], n1 = sn * np[1];
            float u0 = acc[row][cb][0] + n0 + bb0;
            float u1 = acc[row][cb][1] + n1 + bb0;
            float u2 = acc[row][cb][2] + n0 + bb1;
            float u3 = acc[row][cb][3] + n1 + bb1;
            u0 = u0 > 0.f ? u0 : 0.2f * u0;
            u1 = u1 > 0.f ? u1 : 0.2f * u1;
            u2 = u2 > 0.f ? u2 : 0.2f * u2;
            u3 = u3 > 0.f ? u3 : 0.2f * u3;
            *reinterpret_cast<float2*>(op0 + (size_t)gy * r + gx) = make_float2(u0, u1);
            *reinterpret_cast<float2*>(op1 + (size_t)gy * r + gx) = make_float2(u2, u3);
        }
}

// ---------------- ToRGB ------------------------------------------------------
__global__ void k_rgb(const float* __restrict__ xin, float* __restrict__ rgbout,
                      const float* __restrict__ rgb_w, int i, int r) {
    int b = blockIdx.y;
    __shared__ float wr[NF];
    if (threadIdx.x < NF) {
        const float cr = 0.08838834764831843f;  // 1/sqrt(128)
        wr[threadIdx.x] = rgb_w[i * NF + threadIdx.x] * cr * g_s[(i * BSZ + b) * NF + threadIdx.x];
    }
    __syncthreads();
    int p = blockIdx.x * blockDim.x + threadIdx.x;
    if (p >= r * r) return;
    const float* xp = xin + (size_t)b * NF * r * r + p;
    float acc = 0.f;
    #pragma unroll 4
    for (int ci = 0; ci < NF; ci++) acc += wr[ci] * xp[(size_t)ci * r * r];
    rgbout[(size_t)b * r * r + p] = acc;
}

// ---------------- final ------------------------------------------------------
__global__ void k_final(float* __restrict__ out) {
    int idx = blockIdx.x * blockDim.x + threadIdx.x;
    if (idx >= BSZ * IMG * IMG) return;
    int b = idx / (IMG * IMG);
    int rem = idx - b * (IMG * IMG);
    int y = rem >> 8, x = rem & 255;
    float sum = 0.f;
    int roff = 0;
    #pragma unroll
    for (int i = 0; i < 4; i++) {
        int r = 32 << i;
        const float* src = g_rgb + (size_t)BSZ * roff + (size_t)b * r * r;
        float sc = (float)r * (1.f / 256.f);
        float fy = (y + 0.5f) * sc - 0.5f;
        float fx = (x + 0.5f) * sc - 0.5f;
        int iy0 = (int)floorf(fy), ix0 = (int)floorf(fx);
        float ty = fy - iy0, tx = fx - ix0;
        int y0c = max(iy0, 0), y1c = min(iy0 + 1, r - 1);
        int x0c = max(ix0, 0), x1c = min(ix0 + 1, r - 1);
        float v00 = src[y0c * r + x0c], v01 = src[y0c * r + x1c];
        float v10 = src[y1c * r + x0c], v11 = src[y1c * r + x1c];
        float v0 = v00 + tx * (v01 - v00);
        float v1 = v10 + tx * (v11 - v10);
        sum += v0 + ty * (v1 - v0);
        roff += r * r;
    }
    out[idx] = sum * 0.5f + 0.5f;
}

// =============================================================================
static inline int conv_smem_bytes(int TPX) {
    int hw = TPX + 2;
    int x_u32 = 2 * 10 * hw * X_PXS;
    return (W_TOTAL_U32 + x_u32) * 4;
}

extern "C" void kernel_launch(void* const* d_in, const int* in_sizes, int n_in,
                              void* d_out, int out_size) {
    const float* w      = (const float*)d_in[0];
    const float* noise_in[4] = { (const float*)d_in[1], (const float*)d_in[2],
                                 (const float*)d_in[3], (const float*)d_in[4] };
    const float* ic     = (const float*)d_in[5];
    const float* tsw    = (const float*)d_in[6];
    const float* tsb    = (const float*)d_in[7];
    const float* conv_w = (const float*)d_in[8];
    const float* sn     = (const float*)d_in[9];
    const float* sbias  = (const float*)d_in[10];
    const float* rgb_w  = (const float*)d_in[11];
    float* out = (float*)d_out;

    float *xa, *xb, *rgb;
    cudaGetSymbolAddress((void**)&xa, g_xa);
    cudaGetSymbolAddress((void**)&xb, g_xb);
    cudaGetSymbolAddress((void**)&rgb, g_rgb);

    const int smem8  = conv_smem_bytes(8);
    const int smem16 = conv_smem_bytes(16);
    cudaFuncSetAttribute(k_conv_mma<8>,
                         cudaFuncAttributeMaxDynamicSharedMemorySize, smem8);
    cudaFuncSetAttribute(k_conv_mma<16>,
                         cudaFuncAttributeMaxDynamicSharedMemorySize, smem16);

    k_style<<<NB * BSZ, 128>>>(w, tsw, tsb);

    {
        int n = BSZ * NF * 32 * 32;
        k_init<<<(n + 255) / 256, 256>>>(ic, xa);
    }

    float* cur = xa;
    float* tmp = xb;
    int rgboff = 0;
    for (int i = 0; i < NB; i++) {
        int r = 32 << i;
        if (i > 0) {
            int n = BSZ * NF * r * r;
            k_up<<<(n + 255) / 256, 256>>>(cur, tmp, r / 2);
            float* t2 = cur; cur = tmp; tmp = t2;
        }
        for (int j = 0; j < 2; j++) {
            k_modw<<<BSZ * NF, 256>>>(conv_w, i, j);
            const float* nz = noise_in[i] + (size_t)j * BSZ * r * r;
            const float* snp = sn + (i * 2 + j);
            const float* bp = sbias + (i * 2 + j) * NF;
            if (r == 32) {
                dim3 grid(r / 8, r / 8, BSZ);
                k_conv_mma<8><<<grid, 256, smem8>>>(cur, tmp, nz, snp, bp, r);
            } else {
                dim3 grid(r / 16, r / 8, BSZ);
                k_conv_mma<16><<<grid, 256, smem16>>>(cur, tmp, nz, snp, bp, r);
            }
            float* t2 = cur; cur = tmp; tmp = t2;
        }
        dim3 rg((r * r + 255) / 256, BSZ);
        k_rgb<<<rg, 256>>>(cur, rgb + (size_t)BSZ * rgboff, rgb_w, i, r);
        rgboff += r * r;
    }

    {
        int n = BSZ * IMG * IMG;
        k_final<<<(n + 255) / 256, 256>>>(out);
    }
}

// round 17
// speedup vs baseline: 1.1967x; 1.0115x over previous
#include <cuda_runtime.h>
#include <cuda_bf16.h>
#include <math.h>

#define NB    4
#define BSZ   8
#define NF    128
#define WDIM  512
#define IMG   256
#define NCONV 8

// ---------------- scratch (static device globals; no allocation) -------------
__device__ float g_xa[BSZ * NF * IMG * IMG];
__device__ float g_xb[BSZ * NF * IMG * IMG];
__device__ float g_s[NB * BSZ * NF];
__device__ float g_rgb[BSZ * (32*32 + 64*64 + 128*128 + 256*256)];
// pre-split modulated weights for ALL 8 convs:
// [cv(8)][b][chunk(ci/16)][co][tap k][ci2 pair]
__device__ unsigned int g_wsh[NCONV * BSZ * 8 * NF * 72];
__device__ unsigned int g_wsl[NCONV * BSZ * 8 * NF * 72];

// ---------------- helpers ----------------------------------------------------
__device__ __forceinline__ void split2(float v0, float v1,
                                       unsigned int& hi, unsigned int& lo) {
    __nv_bfloat16 h0 = __float2bfloat16(v0);
    __nv_bfloat16 h1 = __float2bfloat16(v1);
    float r0 = v0 - __bfloat162float(h0);
    float r1 = v1 - __bfloat162float(h1);
    __nv_bfloat16 l0 = __float2bfloat16(r0);
    __nv_bfloat16 l1 = __float2bfloat16(r1);
    hi = (unsigned int)__bfloat16_as_ushort(h0) |
         ((unsigned int)__bfloat16_as_ushort(h1) << 16);
    lo = (unsigned int)__bfloat16_as_ushort(l0) |
         ((unsigned int)__bfloat16_as_ushort(l1) << 16);
}

__device__ __forceinline__ void mma16816(float* d, const unsigned int* a,
                                         const unsigned int* b) {
    asm volatile(
        "mma.sync.aligned.m16n8k16.row.col.f32.bf16.bf16.f32 "
        "{%0,%1,%2,%3}, {%4,%5,%6,%7}, {%8,%9}, {%0,%1,%2,%3};\n"
        : "+f"(d[0]), "+f"(d[1]), "+f"(d[2]), "+f"(d[3])
        : "r"(a[0]), "r"(a[1]), "r"(a[2]), "r"(a[3]), "r"(b[0]), "r"(b[1]));
}

__device__ __forceinline__ void cp16(unsigned int* smem_dst, const void* gsrc) {
    unsigned int sa = (unsigned int)__cvta_generic_to_shared(smem_dst);
    asm volatile("cp.async.cg.shared.global [%0], [%1], 16;\n"
                 :: "r"(sa), "l"(gsrc));
}
__device__ __forceinline__ void cp_commit() {
    asm volatile("cp.async.commit_group;\n");
}
__device__ __forceinline__ void cp_wait0() {
    asm volatile("cp.async.wait_group 0;\n");
}

// ---------------- styles -----------------------------------------------------
__global__ void k_style(const float* __restrict__ w, const float* __restrict__ tsw,
                        const float* __restrict__ tsb) {
    int i = blockIdx.x / BSZ, b = blockIdx.x % BSZ;
    int c = threadIdx.x;
    __shared__ float sw[WDIM];
    for (int d = threadIdx.x; d < WDIM; d += blockDim.x)
        sw[d] = w[(i * BSZ + b) * WDIM + d];
    __syncthreads();
    const float* tw = tsw + (i * NF + c) * WDIM;
    float acc = 0.f;
    #pragma unroll 4
    for (int d = 0; d < WDIM; d++) acc += sw[d] * tw[d];
    const float cl = 0.044194173824159216f;   // 1/sqrt(512)
    g_s[(i * BSZ + b) * NF + c] = acc * cl + tsb[i * NF + c];
}

// ---- ALL 8 convs' modulated + demodulated weights in ONE launch -------------
// blockIdx.x = cv * (BSZ*NF) + b * NF + co, cv = i*2+j in 0..7
__global__ void k_modw_all(const float* __restrict__ conv_w) {
    int cv = blockIdx.x >> 10;                 // / (BSZ*NF) = 1024
    int rem = blockIdx.x & 1023;
    int b = rem >> 7, co = rem & 127;
    const float* wsrc = conv_w + (((size_t)cv * NF + co) * NF) * 9;
    const float* s = g_s + ((cv >> 1) * BSZ + b) * NF;
    const float c = 0.029462782549439483f;     // 1/sqrt(128*9)
    __shared__ float buf[NF * 9];
    __shared__ float red[32];
    float ss = 0.f;
    for (int t = threadIdx.x; t < NF * 9; t += blockDim.x) {
        float v = wsrc[t] * c * s[t / 9];
        buf[t] = v;
        ss += v * v;
    }
    for (int o = 16; o; o >>= 1) ss += __shfl_xor_sync(0xffffffffu, ss, o);
    if ((threadIdx.x & 31) == 0) red[threadIdx.x >> 5] = ss;
    __syncthreads();
    if (threadIdx.x < 32) {
        float v = (threadIdx.x < (blockDim.x >> 5)) ? red[threadIdx.x] : 0.f;
        for (int o = 16; o; o >>= 1) v += __shfl_xor_sync(0xffffffffu, v, o);
        if (threadIdx.x == 0) red[0] = v;
    }
    __syncthreads();
    float dem = rsqrtf(red[0] + 1e-8f);
    for (int e = threadIdx.x; e < 576; e += blockDim.x) {
        int ci2g = e / 9, k = e - ci2g * 9;
        int ci = ci2g * 2;
        float v0 = buf[ci * 9 + k] * dem;
        float v1 = buf[ci * 9 + 9 + k] * dem;
        unsigned int hi, lo;
        split2(v0, v1, hi, lo);
        int chunk = ci2g >> 3, p = ci2g & 7;
        size_t idx = (((((size_t)cv * BSZ + b) * 8 + chunk) * NF + co) * 9 + k) * 8 + p;
        g_wsh[idx] = hi;
        g_wsl[idx] = lo;
    }
}

// ---------------- initial constant -------------------------------------------
__global__ void k_init(const float* __restrict__ ic, float* __restrict__ x) {
    int idx = blockIdx.x * blockDim.x + threadIdx.x;
    if (idx >= BSZ * NF * 32 * 32) return;
    int per = NF * 32 * 32;
    float v = ic[idx % per];
    x[idx] = v > 0.f ? v : 0.f;
}

// ---------------- bilinear 2x upsample ---------------------------------------
__global__ void k_up(const float* __restrict__ in, float* __restrict__ out, int rin) {
    int rout = rin * 2;
    int idx = blockIdx.x * blockDim.x + threadIdx.x;
    int total = BSZ * NF * rout * rout;
    if (idx >= total) return;
    int x = idx % rout;
    int t2 = idx / rout;
    int y = t2 % rout;
    int bc = t2 / rout;
    float fy = y * 0.5f - 0.25f, fx = x * 0.5f - 0.25f;
    int iy0 = (int)floorf(fy), ix0 = (int)floorf(fx);
    float ty = fy - iy0, tx = fx - ix0;
    int y0c = max(iy0, 0), y1c = min(iy0 + 1, rin - 1);
    int x0c = max(ix0, 0), x1c = min(ix0 + 1, rin - 1);
    const float* p = in + (size_t)bc * rin * rin;
    float v00 = p[y0c * rin + x0c], v01 = p[y0c * rin + x1c];
    float v10 = p[y1c * rin + x0c], v11 = p[y1c * rin + x1c];
    float v0 = v00 + tx * (v01 - v00);
    float v1 = v10 + tx * (v11 - v10);
    out[idx] = v0 + ty * (v1 - v0);
}

// ---------------- tensor-core modulated conv3x3 ------------------------------
// Row-slide mainloop (R15) + DOUBLE-BUFFERED x smem: store_x(c+1) targets the
// alternate buffer, so only ONE __syncthreads per chunk is needed.
#define W_STRIDE 76
#define X_PXS    12
#define W_BUF_U32 (2 * NF * W_STRIDE)            // hi+lo for one chunk: 19456
#define W_TOTAL_U32 (2 * W_BUF_U32)              // two buffers: 38912

template <int TPX>
__global__ void __launch_bounds__(256, 1)
k_conv_mma(const float* __restrict__ xin, float* __restrict__ xout,
           const float* __restrict__ noise, const float* __restrict__ sn_ptr,
           const float* __restrict__ bias, int r, int cv) {
    constexpr int HW = TPX + 2;
    constexpr int X_PYS = HW * X_PXS;
    constexpr int NCB = TPX / 8;
    constexpr int E = 10 * HW * 8;
    constexpr int MAXE = (E + 255) / 256;
    constexpr int X_BUF_U32 = 2 * 10 * X_PYS;    // hi+lo for one buffer

    extern __shared__ unsigned int dyn[];

    int b = blockIdx.z;
    int x0 = blockIdx.x * TPX, y0 = blockIdx.y * 8;
    int t = threadIdx.x;
    int warp = t >> 5, lane = t & 31;
    int co_w = warp * 16;
    int lq = lane >> 2;
    int lr = lane & 3;

    const size_t rr = (size_t)r * r;

    float acc[8][NCB][4];
    #pragma unroll
    for (int row = 0; row < 8; row++)
        #pragma unroll
        for (int cb = 0; cb < NCB; cb++)
            #pragma unroll
            for (int q = 0; q < 4; q++) acc[row][cb][q] = 0.f;

    // ---- weight async copy helper (restride 72 -> 76), one chunk -> buf
    auto load_w = [&](int chunk, int buf) {
        size_t base4 = (size_t)(((cv * BSZ + b) * 8) + chunk) * (NF * 18);
        const uint4* gh = reinterpret_cast<const uint4*>(g_wsh) + base4;
        const uint4* gl = reinterpret_cast<const uint4*>(g_wsl) + base4;
        unsigned int* wh = dyn + buf * W_BUF_U32;
        unsigned int* wl = wh + NF * W_STRIDE;
        for (int e4 = t; e4 < NF * 18; e4 += 256) {
            int co = e4 / 18, rem = e4 - co * 18;
            cp16(&wh[co * W_STRIDE + rem * 4], gh + e4);
            cp16(&wl[co * W_STRIDE + rem * 4], gl + e4);
        }
    };

    float pv0[MAXE], pv1[MAXE];
    auto fetch_x = [&](int chunk) {
        #pragma unroll
        for (int i = 0; i < MAXE; i++) {
            int e = t + i * 256;
            float v0 = 0.f, v1 = 0.f;
            if (e < E) {
                int p = e & 7;
                int t2 = e >> 3;
                int px = t2 % HW, py = t2 / HW;
                int gy = y0 + py - 1, gx = x0 + px - 1;
                if (gy >= 0 && gy < r && gx >= 0 && gx < r) {
                    const float* pp = xin +
                        (((size_t)(b * NF + chunk * 16 + 2 * p)) * r + gy) * r + gx;
                    v0 = pp[0];
                    v1 = pp[rr];
                }
            }
            pv0[i] = v0;
            pv1[i] = v1;
        }
    };
    auto store_x = [&](int buf) {
        unsigned int* xh = dyn + W_TOTAL_U32 + buf * X_BUF_U32;
        unsigned int* xl = xh + 10 * X_PYS;
        #pragma unroll
        for (int i = 0; i < MAXE; i++) {
            int e = t + i * 256;
            if (e < E) {
                int p = e & 7;
                int t2 = e >> 3;
                int px = t2 % HW, py = t2 / HW;
                unsigned int hi, lo;
                split2(pv0[i], pv1[i], hi, lo);
                int off = py * X_PYS + px * X_PXS + p;
                xh[off] = hi;
                xl[off] = lo;
            }
        }
    };

    // ---- prologue: chunk 0
    load_w(0, 0);
    cp_commit();
    fetch_x(0);
    store_x(0);
    cp_wait0();
    __syncthreads();

    #pragma unroll 1
    for (int chunk = 0; chunk < 8; chunk++) {
        if (chunk < 7) {
            load_w(chunk + 1, (chunk + 1) & 1);
            cp_commit();
            fetch_x(chunk + 1);
        }
        const unsigned int* wh = dyn + (chunk & 1) * W_BUF_U32;
        const unsigned int* wl = wh + NF * W_STRIDE;
        const unsigned int* xh = dyn + W_TOTAL_U32 + (chunk & 1) * X_BUF_U32;
        const unsigned int* xl = xh + 10 * X_PYS;

        // ---- preload all 9 taps' A-fragments
        unsigned int ah[9][4], al[9][4];
        #pragma unroll
        for (int off = 0; off < 9; off++) {
            int wbase = (co_w + lq) * W_STRIDE + off * 8 + lr;
            ah[off][0] = wh[wbase];
            ah[off][1] = wh[wbase + 8 * W_STRIDE];
            ah[off][2] = wh[wbase + 4];
            ah[off][3] = wh[wbase + 8 * W_STRIDE + 4];
            al[off][0] = wl[wbase];
            al[off][1] = wl[wbase + 8 * W_STRIDE];
            al[off][2] = wl[wbase + 4];
            al[off][3] = wl[wbase + 8 * W_STRIDE + 4];
        }

        // ---- row-slide sweep over the 10 smem x-rows
        #pragma unroll
        for (int s = 0; s < 10; s++) {
            #pragma unroll
            for (int cb = 0; cb < NCB; cb++) {
                int base = s * X_PYS + (lq + cb * 8) * X_PXS + lr;
                unsigned int bh0[3], bh1[3], bl0[3], bl1[3];
                #pragma unroll
                for (int kx = 0; kx < 3; kx++) {
                    bh0[kx] = xh[base + kx * X_PXS];
                    bh1[kx] = xh[base + kx * X_PXS + 4];
                    bl0[kx] = xl[base + kx * X_PXS];
                    bl1[kx] = xl[base + kx * X_PXS + 4];
                }
                #pragma unroll
                for (int ky = 0; ky < 3; ky++) {
                    int row = s - ky;
                    if (row >= 0 && row < 8) {
                        #pragma unroll
                        for (int kx = 0; kx < 3; kx++) {
                            unsigned int bh[2] = { bh0[kx], bh1[kx] };
                            unsigned int bl[2] = { bl0[kx], bl1[kx] };
                            int off = ky * 3 + kx;
                            mma16816(acc[row][cb], ah[off], bh);
                            mma16816(acc[row][cb], ah[off], bl);
                            mma16816(acc[row][cb], al[off], bh);
                        }
                    }
                }
            }
        }
        if (chunk < 7) {
            store_x((chunk + 1) & 1);      // other buffer: no pre-sync needed
            cp_wait0();
            __syncthreads();               // single sync per chunk
        }
    }

    // ---- epilogue: noise + bias + leaky relu
    float sn = __ldg(sn_ptr);
    int co0 = co_w + lq, co1 = co0 + 8;
    float bb0 = bias[co0], bb1 = bias[co1];
    float* op0 = xout + ((size_t)(b * NF + co0)) * rr;
    float* op1 = xout + ((size_t)(b * NF + co1)) * rr;
    #pragma unroll
    for (int row = 0; row < 8; row++)
        #pragma unroll
        for (int cb = 0; cb < NCB; cb++) {
            int gy = y0 + row;
            int gx = x0 + cb * 8 + 2 * lr;
            const float* np = noise + ((size_t)b * r + gy) * r + gx;
            float n0 = sn * np[0], n1 = sn * np[1];
            float u0 = acc[row][cb][0] + n0 + bb0;
            float u1 = acc[row][cb][1] + n1 + bb0;
            float u2 = acc[row][cb][2] + n0 + bb1;
            float u3 = acc[row][cb][3] + n1 + bb1;
            u0 = u0 > 0.f ? u0 : 0.2f * u0;
            u1 = u1 > 0.f ? u1 : 0.2f * u1;
            u2 = u2 > 0.f ? u2 : 0.2f * u2;
            u3 = u3 > 0.f ? u3 : 0.2f * u3;
            *reinterpret_cast<float2*>(op0 + (size_t)gy * r + gx) = make_float2(u0, u1);
            *reinterpret_cast<float2*>(op1 + (size_t)gy * r + gx) = make_float2(u2, u3);
        }
}

// ---------------- ToRGB ------------------------------------------------------
__global__ void k_rgb(const float* __restrict__ xin, float* __restrict__ rgbout,
                      const float* __restrict__ rgb_w, int i, int r) {
    int b = blockIdx.y;
    __shared__ float wr[NF];
    if (threadIdx.x < NF) {
        const float cr = 0.08838834764831843f;  // 1/sqrt(128)
        wr[threadIdx.x] = rgb_w[i * NF + threadIdx.x] * cr * g_s[(i * BSZ + b) * NF + threadIdx.x];
    }
    __syncthreads();
    int p = blockIdx.x * blockDim.x + threadIdx.x;
    if (p >= r * r) return;
    const float* xp = xin + (size_t)b * NF * r * r + p;
    float acc = 0.f;
    #pragma unroll 4
    for (int ci = 0; ci < NF; ci++) acc += wr[ci] * xp[(size_t)ci * r * r];
    rgbout[(size_t)b * r * r + p] = acc;
}

// ---------------- final ------------------------------------------------------
__global__ void k_final(float* __restrict__ out) {
    int idx = blockIdx.x * blockDim.x + threadIdx.x;
    if (idx >= BSZ * IMG * IMG) return;
    int b = idx / (IMG * IMG);
    int rem = idx - b * (IMG * IMG);
    int y = rem >> 8, x = rem & 255;
    float sum = 0.f;
    int roff = 0;
    #pragma unroll
    for (int i = 0; i < 4; i++) {
        int r = 32 << i;
        const float* src = g_rgb + (size_t)BSZ * roff + (size_t)b * r * r;
        float sc = (float)r * (1.f / 256.f);
        float fy = (y + 0.5f) * sc - 0.5f;
        float fx = (x + 0.5f) * sc - 0.5f;
        int iy0 = (int)floorf(fy), ix0 = (int)floorf(fx);
        float ty = fy - iy0, tx = fx - ix0;
        int y0c = max(iy0, 0), y1c = min(iy0 + 1, r - 1);
        int x0c = max(ix0, 0), x1c = min(ix0 + 1, r - 1);
        float v00 = src[y0c * r + x0c], v01 = src[y0c * r + x1c];
        float v10 = src[y1c * r + x0c], v11 = src[y1c * r + x1c];
        float v0 = v00 + tx * (v01 - v00);
        float v1 = v10 + tx * (v11 - v10);
        sum += v0 + ty * (v1 - v0);
        roff += r * r;
    }
    out[idx] = sum * 0.5f + 0.5f;
}

// =============================================================================
static inline int conv_smem_bytes(int TPX) {
    int hw = TPX + 2;
    int x_u32 = 2 * 2 * 10 * hw * X_PXS;         // double-buffered hi+lo
    return (W_TOTAL_U32 + x_u32) * 4;
}

extern "C" void kernel_launch(void* const* d_in, const int* in_sizes, int n_in,
                              void* d_out, int out_size) {
    const float* w      = (const float*)d_in[0];
    const float* noise_in[4] = { (const float*)d_in[1], (const float*)d_in[2],
                                 (const float*)d_in[3], (const float*)d_in[4] };
    const float* ic     = (const float*)d_in[5];
    const float* tsw    = (const float*)d_in[6];
    const float* tsb    = (const float*)d_in[7];
    const float* conv_w = (const float*)d_in[8];
    const float* sn     = (const float*)d_in[9];
    const float* sbias  = (const float*)d_in[10];
    const float* rgb_w  = (const float*)d_in[11];
    float* out = (float*)d_out;

    float *xa, *xb, *rgb;
    cudaGetSymbolAddress((void**)&xa, g_xa);
    cudaGetSymbolAddress((void**)&xb, g_xb);
    cudaGetSymbolAddress((void**)&rgb, g_rgb);

    const int smem8  = conv_smem_bytes(8);
    const int smem16 = conv_smem_bytes(16);
    cudaFuncSetAttribute(k_conv_mma<8>,
                         cudaFuncAttributeMaxDynamicSharedMemorySize, smem8);
    cudaFuncSetAttribute(k_conv_mma<16>,
                         cudaFuncAttributeMaxDynamicSharedMemorySize, smem16);

    k_style<<<NB * BSZ, 128>>>(w, tsw, tsb);

    // ALL 8 convs' weight prep in one launch (depends only on styles)
    k_modw_all<<<NCONV * BSZ * NF, 256>>>(conv_w);

    {
        int n = BSZ * NF * 32 * 32;
        k_init<<<(n + 255) / 256, 256>>>(ic, xa);
    }

    float* cur = xa;
    float* tmp = xb;
    int rgboff = 0;
    for (int i = 0; i < NB; i++) {
        int r = 32 << i;
        if (i > 0) {
            int n = BSZ * NF * r * r;
            k_up<<<(n + 255) / 256, 256>>>(cur, tmp, r / 2);
            float* t2 = cur; cur = tmp; tmp = t2;
        }
        for (int j = 0; j < 2; j++) {
            int cv = i * 2 + j;
            const float* nz = noise_in[i] + (size_t)j * BSZ * r * r;
            const float* snp = sn + cv;
            const float* bp = sbias + cv * NF;
            if (r == 32) {
                dim3 grid(r / 8, r / 8, BSZ);
                k_conv_mma<8><<<grid, 256, smem8>>>(cur, tmp, nz, snp, bp, r, cv);
            } else {
                dim3 grid(r / 16, r / 8, BSZ);
                k_conv_mma<16><<<grid, 256, smem16>>>(cur, tmp, nz, snp, bp, r, cv);
            }
            float* t2 = cur; cur = tmp; tmp = t2;
        }
        dim3 rg((r * r + 255) / 256, BSZ);
        k_rgb<<<rg, 256>>>(cur, rgb + (size_t)BSZ * rgboff, rgb_w, i, r);
        rgboff += r * r;
    }

    {
        int n = BSZ * IMG * IMG;
        k_final<<<(n + 255) / 256, 256>>>(out);
    }
}